// round 2
// baseline (speedup 1.0000x reference)
#include <cuda_runtime.h>
#include <cuda_bf16.h>

#define S_LEN 512
#define B_DIM 256
#define Z_DIM 64

// ---------------------------------------------------------------------------
// Forward pass: alpha[t] = e[t] * (alpha[t-1] @ T^T)
// One CTA per batch, 64 threads (thread j owns state j).
// (a @ T^T)[j] = sum_i a_i * T[j][i]  -> thread j holds ROW j of T in regs.
// ---------------------------------------------------------------------------
__global__ __launch_bounds__(Z_DIM)
void hmm_alpha_kernel(const int* __restrict__ inp,      // [S, B]
                      const float* __restrict__ T,      // [Z, Z]
                      const float* __restrict__ pi,     // [Z]
                      const float* __restrict__ emit,   // [X, Z]
                      float* __restrict__ alpha)        // [S, B, Z]
{
    const int b = blockIdx.x;
    const int j = threadIdx.x;

    __shared__ float a_sh[Z_DIM];
    __shared__ int   x_sh[S_LEN];

    #pragma unroll
    for (int t = j; t < S_LEN; t += Z_DIM) x_sh[t] = inp[t * B_DIM + b];

    float Trow[Z_DIM];
    #pragma unroll
    for (int i = 0; i < Z_DIM; i += 4) {
        float4 v = *reinterpret_cast<const float4*>(&T[j * Z_DIM + i]);
        Trow[i] = v.x; Trow[i+1] = v.y; Trow[i+2] = v.z; Trow[i+3] = v.w;
    }
    __syncthreads();

    // t = 0
    float a = emit[x_sh[0] * Z_DIM + j] * pi[j];
    alpha[(size_t)0 * B_DIM * Z_DIM + b * Z_DIM + j] = a;
    a_sh[j] = a;
    float e_next = emit[x_sh[1] * Z_DIM + j];   // prefetch e[1]
    __syncthreads();

    for (int t = 1; t < S_LEN; t++) {
        const float4* a4 = reinterpret_cast<const float4*>(a_sh);
        float acc0 = 0.f, acc1 = 0.f, acc2 = 0.f, acc3 = 0.f;
        #pragma unroll
        for (int k = 0; k < Z_DIM / 4; k++) {
            float4 v = a4[k];
            acc0 = fmaf(v.x, Trow[4*k + 0], acc0);
            acc1 = fmaf(v.y, Trow[4*k + 1], acc1);
            acc2 = fmaf(v.z, Trow[4*k + 2], acc2);
            acc3 = fmaf(v.w, Trow[4*k + 3], acc3);
        }
        a = e_next * ((acc0 + acc1) + (acc2 + acc3));

        alpha[(size_t)t * B_DIM * Z_DIM + b * Z_DIM + j] = a;

        if (t + 1 < S_LEN) e_next = emit[x_sh[t + 1] * Z_DIM + j];

        __syncthreads();          // all threads done reading old a_sh
        a_sh[j] = a;
        __syncthreads();          // new a_sh visible
    }
}

// ---------------------------------------------------------------------------
// Backward pass + posterior:
//   c[t+1] = e[t+1] * beta[t+1];  beta[t] = c[t+1] @ T
//   beta[t][i] = sum_j c_j * T[j][i]  -> thread i holds COLUMN i of T in regs.
//   posterior[t] = alpha[t]*beta[t] / sum_z(alpha[t]*beta[t])
// ---------------------------------------------------------------------------
__global__ __launch_bounds__(Z_DIM)
void hmm_beta_kernel(const int* __restrict__ inp,
                     const float* __restrict__ T,
                     const float* __restrict__ emit,
                     const float* __restrict__ alpha,  // [S, B, Z]
                     float* __restrict__ beta,         // [S, B, Z]
                     float* __restrict__ post)         // [S, B, Z]
{
    const int b = blockIdx.x;
    const int i = threadIdx.x;
    const int lane = i & 31;
    const int w    = i >> 5;

    __shared__ float c_sh[Z_DIM];
    __shared__ int   x_sh[S_LEN];
    __shared__ float wsum_sh[2];

    #pragma unroll
    for (int t = i; t < S_LEN; t += Z_DIM) x_sh[t] = inp[t * B_DIM + b];

    // COLUMN i of T: Tcol[k] = T[k][i]  (coalesced across threads per k)
    float Tcol[Z_DIM];
    #pragma unroll
    for (int k = 0; k < Z_DIM; k++) {
        Tcol[k] = T[k * Z_DIM + i];
    }
    __syncthreads();

    // t = S-1 : beta = 1
    {
        const size_t off = (size_t)(S_LEN - 1) * B_DIM * Z_DIM + b * Z_DIM + i;
        float bt = 1.0f;
        beta[off] = bt;
        float ab = alpha[off] * bt;
        float s = ab;
        #pragma unroll
        for (int o = 16; o > 0; o >>= 1) s += __shfl_xor_sync(0xffffffffu, s, o);
        if (lane == 0) wsum_sh[w] = s;
        c_sh[i] = emit[x_sh[S_LEN - 1] * Z_DIM + i] * bt;
        __syncthreads();
        float tot = wsum_sh[0] + wsum_sh[1];
        post[off] = ab / tot;
        __syncthreads();
    }

    // prefetch for t = S-2
    float al_cur = alpha[(size_t)(S_LEN - 2) * B_DIM * Z_DIM + b * Z_DIM + i];
    float e_cur  = emit[x_sh[S_LEN - 2] * Z_DIM + i];

    for (int t = S_LEN - 2; t >= 0; t--) {
        // bt[i] = dot(c_sh, Tcol)
        const float4* c4 = reinterpret_cast<const float4*>(c_sh);
        float acc0 = 0.f, acc1 = 0.f, acc2 = 0.f, acc3 = 0.f;
        #pragma unroll
        for (int k = 0; k < Z_DIM / 4; k++) {
            float4 v = c4[k];
            acc0 = fmaf(v.x, Tcol[4*k + 0], acc0);
            acc1 = fmaf(v.y, Tcol[4*k + 1], acc1);
            acc2 = fmaf(v.z, Tcol[4*k + 2], acc2);
            acc3 = fmaf(v.w, Tcol[4*k + 3], acc3);
        }
        float bt = (acc0 + acc1) + (acc2 + acc3);

        const size_t off = (size_t)t * B_DIM * Z_DIM + b * Z_DIM + i;
        beta[off] = bt;

        float ab = al_cur * bt;
        float s = ab;
        #pragma unroll
        for (int o = 16; o > 0; o >>= 1) s += __shfl_xor_sync(0xffffffffu, s, o);
        if (lane == 0) wsum_sh[w] = s;

        float c_new = e_cur * bt;

        // prefetch for t-1 (off critical path)
        if (t > 0) {
            al_cur = alpha[off - (size_t)B_DIM * Z_DIM];
            e_cur  = emit[x_sh[t - 1] * Z_DIM + i];
        }

        __syncthreads();           // c_sh reads done; wsum_sh visible
        c_sh[i] = c_new;
        float tot = wsum_sh[0] + wsum_sh[1];
        post[off] = ab / tot;
        __syncthreads();           // new c_sh visible; wsum reads done
    }
}

extern "C" void kernel_launch(void* const* d_in, const int* in_sizes, int n_in,
                              void* d_out, int out_size)
{
    const int*   inp  = (const int*)  d_in[0];   // [512, 256] int32
    const float* T    = (const float*)d_in[1];   // [64, 64]
    const float* pi   = (const float*)d_in[2];   // [64]
    const float* emit = (const float*)d_in[3];   // [10000, 64]

    float* out   = (float*)d_out;
    const size_t N = (size_t)S_LEN * B_DIM * Z_DIM;
    float* alpha = out;
    float* beta  = out + N;
    float* post  = out + 2 * N;

    hmm_alpha_kernel<<<B_DIM, Z_DIM>>>(inp, T, pi, emit, alpha);
    hmm_beta_kernel <<<B_DIM, Z_DIM>>>(inp, T, emit, alpha, beta, post);
}

// round 3
// speedup vs baseline: 2.4033x; 2.4033x over previous
#include <cuda_runtime.h>
#include <cuda_bf16.h>

#define S_LEN 512
#define B_DIM 256
#define Z_DIM 64

// ---------------------------------------------------------------------------
// Fused forward/backward recursions (independent of each other):
//   blocks [0, 256):   alpha[t] = e[t] * (alpha[t-1] @ T^T)
//   blocks [256, 512): beta[t]  = (e[t+1] * beta[t+1]) @ T
// One CTA per (batch, direction), 64 threads, thread z owns state z.
// T row/column in registers; recurrent vector through double-buffered smem
// with ONE barrier per step.
// ---------------------------------------------------------------------------
__global__ __launch_bounds__(Z_DIM)
void hmm_fb_kernel(const int* __restrict__ inp,      // [S, B]
                   const float* __restrict__ T,      // [Z, Z]
                   const float* __restrict__ pi,     // [Z]
                   const float* __restrict__ emit,   // [X, Z]
                   float* __restrict__ alpha,        // [S, B, Z]
                   float* __restrict__ beta)         // [S, B, Z]
{
    const bool bwd = blockIdx.x >= B_DIM;
    const int  b   = blockIdx.x & (B_DIM - 1);
    const int  z   = threadIdx.x;

    __shared__ float v_sh[2][Z_DIM];
    __shared__ int   x_sh[S_LEN];

    #pragma unroll
    for (int t = z; t < S_LEN; t += Z_DIM) x_sh[t] = inp[t * B_DIM + b];

    // Forward needs ROW z of T (sum_i a_i*T[z][i]); backward needs COLUMN z
    // (sum_j c_j*T[j][z]).
    float Tr[Z_DIM];
    if (!bwd) {
        #pragma unroll
        for (int k = 0; k < Z_DIM; k += 4) {
            float4 v = *reinterpret_cast<const float4*>(&T[z * Z_DIM + k]);
            Tr[k] = v.x; Tr[k+1] = v.y; Tr[k+2] = v.z; Tr[k+3] = v.w;
        }
    } else {
        #pragma unroll
        for (int k = 0; k < Z_DIM; k++) Tr[k] = T[k * Z_DIM + z];
    }
    __syncthreads();

    if (!bwd) {
        // ---------------- forward ----------------
        float a = emit[x_sh[0] * Z_DIM + z] * pi[z];
        alpha[(size_t)b * Z_DIM + z] = a;
        v_sh[0][z] = a;
        float e_next = emit[x_sh[1] * Z_DIM + z];
        __syncthreads();

        for (int t = 1; t < S_LEN; t++) {
            const float4* a4 = reinterpret_cast<const float4*>(v_sh[(t - 1) & 1]);
            float c0=0.f,c1=0.f,c2=0.f,c3=0.f,c4=0.f,c5=0.f,c6=0.f,c7=0.f;
            #pragma unroll
            for (int k = 0; k < 8; k++) {
                float4 u = a4[2*k], w = a4[2*k + 1];
                c0 = fmaf(u.x, Tr[8*k+0], c0);
                c1 = fmaf(u.y, Tr[8*k+1], c1);
                c2 = fmaf(u.z, Tr[8*k+2], c2);
                c3 = fmaf(u.w, Tr[8*k+3], c3);
                c4 = fmaf(w.x, Tr[8*k+4], c4);
                c5 = fmaf(w.y, Tr[8*k+5], c5);
                c6 = fmaf(w.z, Tr[8*k+6], c6);
                c7 = fmaf(w.w, Tr[8*k+7], c7);
            }
            a = e_next * (((c0+c1)+(c2+c3)) + ((c4+c5)+(c6+c7)));

            alpha[(size_t)t * B_DIM * Z_DIM + b * Z_DIM + z] = a;
            v_sh[t & 1][z] = a;
            if (t + 1 < S_LEN) e_next = emit[x_sh[t + 1] * Z_DIM + z];
            __syncthreads();
        }
    } else {
        // ---------------- backward ----------------
        float bt = 1.0f;
        beta[(size_t)(S_LEN - 1) * B_DIM * Z_DIM + b * Z_DIM + z] = bt;
        v_sh[(S_LEN - 1) & 1][z] = emit[x_sh[S_LEN - 1] * Z_DIM + z] * bt; // c[S-1]
        float e_cur = emit[x_sh[S_LEN - 2] * Z_DIM + z];
        __syncthreads();

        for (int t = S_LEN - 2; t >= 0; t--) {
            const float4* c4p = reinterpret_cast<const float4*>(v_sh[(t + 1) & 1]);
            float c0=0.f,c1=0.f,c2=0.f,c3=0.f,c4=0.f,c5=0.f,c6=0.f,c7=0.f;
            #pragma unroll
            for (int k = 0; k < 8; k++) {
                float4 u = c4p[2*k], w = c4p[2*k + 1];
                c0 = fmaf(u.x, Tr[8*k+0], c0);
                c1 = fmaf(u.y, Tr[8*k+1], c1);
                c2 = fmaf(u.z, Tr[8*k+2], c2);
                c3 = fmaf(u.w, Tr[8*k+3], c3);
                c4 = fmaf(w.x, Tr[8*k+4], c4);
                c5 = fmaf(w.y, Tr[8*k+5], c5);
                c6 = fmaf(w.z, Tr[8*k+6], c6);
                c7 = fmaf(w.w, Tr[8*k+7], c7);
            }
            bt = ((c0+c1)+(c2+c3)) + ((c4+c5)+(c6+c7));

            beta[(size_t)t * B_DIM * Z_DIM + b * Z_DIM + z] = bt;
            v_sh[t & 1][z] = e_cur * bt;            // c[t] for next step
            if (t > 0) e_cur = emit[x_sh[t - 1] * Z_DIM + z];
            __syncthreads();
        }
    }
}

// ---------------------------------------------------------------------------
// Posterior: post = alpha*beta / sum_z(alpha*beta). Fully parallel, streaming.
// 16 lanes per (t,b) row; each lane handles a float4 (16*4 = 64 states).
// ---------------------------------------------------------------------------
__global__ __launch_bounds__(256)
void hmm_post_kernel(const float* __restrict__ alpha,
                     const float* __restrict__ beta,
                     float* __restrict__ post)
{
    const int gid = blockIdx.x * blockDim.x + threadIdx.x;
    const int row = gid >> 4;           // (t, b) row index, S*B rows total
    const int sub = gid & 15;

    const size_t off = (size_t)row * Z_DIM + sub * 4;
    float4 av = *reinterpret_cast<const float4*>(alpha + off);
    float4 bv = *reinterpret_cast<const float4*>(beta  + off);

    float4 ab;
    ab.x = av.x * bv.x; ab.y = av.y * bv.y;
    ab.z = av.z * bv.z; ab.w = av.w * bv.w;

    float s = (ab.x + ab.y) + (ab.z + ab.w);
    #pragma unroll
    for (int o = 8; o > 0; o >>= 1) s += __shfl_xor_sync(0xffffffffu, s, o);

    float inv = 1.0f / s;
    float4 p;
    p.x = ab.x * inv; p.y = ab.y * inv; p.z = ab.z * inv; p.w = ab.w * inv;
    *reinterpret_cast<float4*>(post + off) = p;
}

extern "C" void kernel_launch(void* const* d_in, const int* in_sizes, int n_in,
                              void* d_out, int out_size)
{
    const int*   inp  = (const int*)  d_in[0];   // [512, 256] int32
    const float* T    = (const float*)d_in[1];   // [64, 64]
    const float* pi   = (const float*)d_in[2];   // [64]
    const float* emit = (const float*)d_in[3];   // [10000, 64]

    float* out   = (float*)d_out;
    const size_t N = (size_t)S_LEN * B_DIM * Z_DIM;
    float* alpha = out;
    float* beta  = out + N;
    float* post  = out + 2 * N;

    hmm_fb_kernel<<<2 * B_DIM, Z_DIM>>>(inp, T, pi, emit, alpha, beta);

    const int rows = S_LEN * B_DIM;             // 131072
    const int threads = 256;
    const int blocks = rows * 16 / threads;     // 8192
    hmm_post_kernel<<<blocks, threads>>>(alpha, beta, post);
}

// round 5
// speedup vs baseline: 2.5323x; 1.0537x over previous
#include <cuda_runtime.h>
#include <cuda_bf16.h>

#define S_LEN 512
#define B_DIM 256
#define Z_DIM 64

// ---- packed f32x2 helpers (full fp32 precision, 2 MACs per instruction) ----
__device__ __forceinline__ unsigned long long pack2(float lo, float hi) {
    unsigned long long r;
    asm("mov.b64 %0, {%1, %2};" : "=l"(r) : "f"(lo), "f"(hi));
    return r;
}
__device__ __forceinline__ unsigned long long fma2(unsigned long long a,
                                                   unsigned long long b,
                                                   unsigned long long c) {
    unsigned long long d;
    asm("fma.rn.f32x2 %0, %1, %2, %3;" : "=l"(d) : "l"(a), "l"(b), "l"(c));
    return d;
}
__device__ __forceinline__ unsigned long long add2(unsigned long long a,
                                                   unsigned long long b) {
    unsigned long long d;
    asm("add.rn.f32x2 %0, %1, %2;" : "=l"(d) : "l"(a), "l"(b));
    return d;
}
__device__ __forceinline__ float hsum2(unsigned long long v) {
    float lo, hi;
    asm("mov.b64 {%0, %1}, %2;" : "=f"(lo), "=f"(hi) : "l"(v));
    return lo + hi;
}

// ---------------------------------------------------------------------------
// Fused forward/backward recursions (independent; run concurrently):
//   blocks [0,256):   alpha[t] = e[t] * (alpha[t-1] @ T^T)   (thread z: ROW z)
//   blocks [256,512): beta[t]  = (e[t+1]*beta[t+1]) @ T      (thread z: COL z)
// 64 threads/CTA. T packed K-pairwise into 32 f32x2 regs. Recurrent vector via
// double-buffered smem, ONE barrier/step. Emission gather: depth-4 reg ring.
// ---------------------------------------------------------------------------
__global__ __launch_bounds__(Z_DIM)
void hmm_fb_kernel(const int* __restrict__ inp,      // [S, B]
                   const float* __restrict__ T,      // [Z, Z]
                   const float* __restrict__ pi,     // [Z]
                   const float* __restrict__ emit,   // [X, Z]
                   float* __restrict__ alpha,        // [S, B, Z]
                   float* __restrict__ beta)         // [S, B, Z]
{
    const bool bwd = blockIdx.x >= B_DIM;
    const int  b   = blockIdx.x & (B_DIM - 1);
    const int  z   = threadIdx.x;

    __shared__ __align__(16) float v_sh[2][Z_DIM];
    __shared__ int x_sh[S_LEN];

    #pragma unroll
    for (int t = z; t < S_LEN; t += Z_DIM) x_sh[t] = inp[t * B_DIM + b];

    // T packed: fwd -> row z pairs {T[z][2k],T[z][2k+1]}
    //           bwd -> col z pairs {T[2k][z],T[2k+1][z]}
    unsigned long long Tp[Z_DIM / 2];
    if (!bwd) {
        #pragma unroll
        for (int k = 0; k < Z_DIM; k += 4) {
            float4 v = *reinterpret_cast<const float4*>(&T[z * Z_DIM + k]);
            Tp[k / 2]     = pack2(v.x, v.y);
            Tp[k / 2 + 1] = pack2(v.z, v.w);
        }
    } else {
        #pragma unroll
        for (int k = 0; k < Z_DIM; k += 2) {
            Tp[k / 2] = pack2(T[k * Z_DIM + z], T[(k + 1) * Z_DIM + z]);
        }
    }
    __syncthreads();

#define DOT64(buf, result)                                                     \
    {                                                                          \
        const ulonglong2* p2 = reinterpret_cast<const ulonglong2*>(buf);       \
        unsigned long long s0 = 0, s1 = 0, s2 = 0, s3 = 0,                     \
                           s4 = 0, s5 = 0, s6 = 0, s7 = 0;                     \
        _Pragma("unroll")                                                      \
        for (int q = 0; q < 4; q++) {                                          \
            ulonglong2 u0 = p2[4 * q + 0];                                     \
            ulonglong2 u1 = p2[4 * q + 1];                                     \
            ulonglong2 u2 = p2[4 * q + 2];                                     \
            ulonglong2 u3 = p2[4 * q + 3];                                     \
            s0 = fma2(u0.x, Tp[8 * q + 0], s0);                                \
            s1 = fma2(u0.y, Tp[8 * q + 1], s1);                                \
            s2 = fma2(u1.x, Tp[8 * q + 2], s2);                                \
            s3 = fma2(u1.y, Tp[8 * q + 3], s3);                                \
            s4 = fma2(u2.x, Tp[8 * q + 4], s4);                                \
            s5 = fma2(u2.y, Tp[8 * q + 5], s5);                                \
            s6 = fma2(u3.x, Tp[8 * q + 6], s6);                                \
            s7 = fma2(u3.y, Tp[8 * q + 7], s7);                                \
        }                                                                      \
        unsigned long long sA = add2(add2(s0, s1), add2(s2, s3));              \
        unsigned long long sB = add2(add2(s4, s5), add2(s6, s7));              \
        result = hsum2(add2(sA, sB));                                          \
    }

    if (!bwd) {
        // ---------------- forward ----------------
        float e_ring[4];
        float a = emit[x_sh[0] * Z_DIM + z] * pi[z];
        alpha[(size_t)b * Z_DIM + z] = a;
        v_sh[0][z] = a;
        #pragma unroll
        for (int q = 1; q <= 4; q++)
            e_ring[q & 3] = emit[x_sh[q] * Z_DIM + z];
        __syncthreads();

        for (int t = 1; t < S_LEN; t++) {
            float dot;
            DOT64(v_sh[(t - 1) & 1], dot);
            float e_t = e_ring[t & 3];
            if (t + 4 < S_LEN) e_ring[t & 3] = emit[x_sh[t + 4] * Z_DIM + z];
            a = e_t * dot;

            alpha[(size_t)t * B_DIM * Z_DIM + b * Z_DIM + z] = a;
            v_sh[t & 1][z] = a;
            __syncthreads();
        }
    } else {
        // ---------------- backward ----------------
        float e_ring[4];
        float bt = 1.0f;
        beta[(size_t)(S_LEN - 1) * B_DIM * Z_DIM + b * Z_DIM + z] = bt;
        v_sh[(S_LEN - 1) & 1][z] = emit[x_sh[S_LEN - 1] * Z_DIM + z]; // c[S-1]
        #pragma unroll
        for (int q = 2; q <= 5; q++)
            e_ring[(S_LEN - q) & 3] = emit[x_sh[S_LEN - q] * Z_DIM + z];
        __syncthreads();

        for (int t = S_LEN - 2; t >= 0; t--) {
            float dot;
            DOT64(v_sh[(t + 1) & 1], dot);
            float e_t = e_ring[t & 3];
            if (t - 4 >= 0) e_ring[t & 3] = emit[x_sh[t - 4] * Z_DIM + z];
            bt = dot;

            beta[(size_t)t * B_DIM * Z_DIM + b * Z_DIM + z] = bt;
            v_sh[t & 1][z] = e_t * bt;          // c[t] for next step
            __syncthreads();
        }
    }
#undef DOT64
}

// ---------------------------------------------------------------------------
// Posterior: post = alpha*beta / sum_z(alpha*beta). Streaming, HBM-bound.
// 16 lanes per (t,b) row; each lane handles a float4.
// ---------------------------------------------------------------------------
__global__ __launch_bounds__(256)
void hmm_post_kernel(const float* __restrict__ alpha,
                     const float* __restrict__ beta,
                     float* __restrict__ post)
{
    const int gid = blockIdx.x * blockDim.x + threadIdx.x;
    const int row = gid >> 4;
    const int sub = gid & 15;

    const size_t off = (size_t)row * Z_DIM + sub * 4;
    float4 av = *reinterpret_cast<const float4*>(alpha + off);
    float4 bv = *reinterpret_cast<const float4*>(beta  + off);

    float4 ab;
    ab.x = av.x * bv.x; ab.y = av.y * bv.y;
    ab.z = av.z * bv.z; ab.w = av.w * bv.w;

    float s = (ab.x + ab.y) + (ab.z + ab.w);
    #pragma unroll
    for (int o = 8; o > 0; o >>= 1) s += __shfl_xor_sync(0xffffffffu, s, o);

    float inv = 1.0f / s;
    float4 p;
    p.x = ab.x * inv; p.y = ab.y * inv; p.z = ab.z * inv; p.w = ab.w * inv;
    *reinterpret_cast<float4*>(post + off) = p;
}

extern "C" void kernel_launch(void* const* d_in, const int* in_sizes, int n_in,
                              void* d_out, int out_size)
{
    const int*   inp  = (const int*)  d_in[0];   // [512, 256] int32
    const float* T    = (const float*)d_in[1];   // [64, 64]
    const float* pi   = (const float*)d_in[2];   // [64]
    const float* emit = (const float*)d_in[3];   // [10000, 64]

    float* out   = (float*)d_out;
    const size_t N = (size_t)S_LEN * B_DIM * Z_DIM;
    float* alpha = out;
    float* beta  = out + N;
    float* post  = out + 2 * N;

    hmm_fb_kernel<<<2 * B_DIM, Z_DIM>>>(inp, T, pi, emit, alpha, beta);

    const int rows = S_LEN * B_DIM;             // 131072
    const int threads = 256;
    const int blocks = rows * 16 / threads;     // 8192
    hmm_post_kernel<<<blocks, threads>>>(alpha, beta, post);
}